// round 1
// baseline (speedup 1.0000x reference)
#include <cuda_runtime.h>
#include <cstddef>

// ---------------- problem constants ----------------
#define BB   2
#define TT   2048
#define CC   1024
#define NH   16
#define NKV  4
#define HD   64
#define KVC  (NKV * HD)       // 256
#define MM   (BB * TT)        // 4096
// ln(10000)/64
#define ROPE_C 0.14391156831212787f

// ---------------- scratch (device globals; no allocs allowed) ----------------
__device__ float g_q  [MM * CC];
__device__ float g_k  [MM * KVC];
__device__ float g_v  [MM * KVC];
__device__ float g_att[MM * CC];

// ---------------- SGEMM: C = A @ W + bias, optional interleaved-RoPE epilogue ----
// A: [M,K] row-major, W: [K,N] row-major, C: [M,N] row-major
// 64x64 block tile, 4x4 per-thread micro-tile, BK=16, 256 threads.
template<bool ROPE>
__global__ void __launch_bounds__(256)
sgemm_kernel(const float* __restrict__ A, const float* __restrict__ W,
             const float* __restrict__ bias, float* __restrict__ Cmat,
             int M, int N, int K)
{
    __shared__ float As[16][68];   // [kk][m], padded for float4-aligned reads
    __shared__ float Bs[16][64];   // [kk][n]

    const int tid = threadIdx.x;
    const int tx  = tid & 15;
    const int ty  = tid >> 4;
    const int row0 = blockIdx.y * 64;
    const int col0 = blockIdx.x * 64;

    float acc[4][4] = {};

    for (int k0 = 0; k0 < K; k0 += 16) {
        #pragma unroll
        for (int i = 0; i < 4; i++) {
            int e  = tid + i * 256;
            int m  = e >> 4;
            int kk = e & 15;
            As[kk][m] = A[(size_t)(row0 + m) * K + k0 + kk];
        }
        #pragma unroll
        for (int i = 0; i < 4; i++) {
            int e  = tid + i * 256;
            int kk = e >> 6;
            int n  = e & 63;
            Bs[kk][n] = W[(size_t)(k0 + kk) * N + col0 + n];
        }
        __syncthreads();

        #pragma unroll
        for (int kk = 0; kk < 16; kk++) {
            float a[4], b[4];
            *(float4*)a = *(const float4*)&As[kk][ty * 4];
            *(float4*)b = *(const float4*)&Bs[kk][tx * 4];
            #pragma unroll
            for (int i = 0; i < 4; i++)
                #pragma unroll
                for (int j = 0; j < 4; j++)
                    acc[i][j] = fmaf(a[i], b[j], acc[i][j]);
        }
        __syncthreads();
    }

    // epilogue: bias (+ RoPE)
    #pragma unroll
    for (int i = 0; i < 4; i++) {
        const int row = row0 + ty * 4 + i;
        const int t   = row & (TT - 1);
        #pragma unroll
        for (int j = 0; j < 4; j++)
            acc[i][j] += bias[col0 + tx * 4 + j];

        if (ROPE) {
            #pragma unroll
            for (int p = 0; p < 2; p++) {
                const int col = col0 + tx * 4 + 2 * p;
                const int d   = col & (HD - 1);      // even; equals 2*pair_index
                float inv = expf(-(float)d * ROPE_C);
                float ang = (float)t * inv;
                float sn, cs;
                sincosf(ang, &sn, &cs);
                float e = acc[i][2 * p];
                float o = acc[i][2 * p + 1];
                acc[i][2 * p]     = e * cs - o * sn;
                acc[i][2 * p + 1] = e * sn + o * cs;
            }
        }
        #pragma unroll
        for (int j = 0; j < 4; j++)
            Cmat[(size_t)row * N + col0 + tx * 4 + j] = acc[i][j];
    }
}

// ---------------- Flash attention (fp32, causal, GQA) ----------------
// Grid: (T/64, NH, B). Block: 256 threads = 16x16, 4x4 micro-tiles.
// smem: Qs[64][68] ([hd][row]) + Ks[64][68] ([hd][col], reused as P^T [col][row])
//       + Vs[64][64] ([col][hd]) = 51200 bytes (dynamic).
#define ATT_SMEM ((64 * 68 + 64 * 68 + 64 * 64) * 4)

__global__ void __launch_bounds__(256)
attn_kernel(const float* __restrict__ Qm, const float* __restrict__ Km,
            const float* __restrict__ Vm, float* __restrict__ Om)
{
    extern __shared__ float sm[];
    float* Qs = sm;                 // stride 68: Qs[kk*68 + r]
    float* Ks = sm + 64 * 68;       // stride 68: Ks[kk*68 + c]  (later P^T[c*68 + r])
    float* Vs = sm + 2 * 64 * 68;   // stride 64: Vs[c*64 + d]

    const int b  = blockIdx.z;
    const int h  = blockIdx.y;
    const int qt = blockIdx.x;
    const int kvh = h >> 2;         // repeat_interleave: head h uses kv head h/4
    const int tid = threadIdx.x;
    const int tx  = tid & 15;
    const int ty  = tid >> 4;

    // load Q tile (transposed to [hd][row]) with 1/sqrt(hd) folded in
    const float* qb = Qm + ((size_t)(b * TT + qt * 64)) * CC + h * HD;
    #pragma unroll
    for (int i = 0; i < 16; i++) {
        int e  = tid + i * 256;
        int r  = e >> 6;
        int kk = e & 63;
        Qs[kk * 68 + r] = qb[(size_t)r * CC + kk] * 0.125f;
    }

    float m[4], l[4], o[4][4];
    #pragma unroll
    for (int i = 0; i < 4; i++) {
        m[i] = -3.0e38f;
        l[i] = 0.f;
        #pragma unroll
        for (int j = 0; j < 4; j++) o[i][j] = 0.f;
    }

    for (int j = 0; j <= qt; j++) {
        __syncthreads();   // previous iteration finished reading Ks(P^T)/Vs; Qs ready (iter 0)

        const float* kb = Km + ((size_t)(b * TT + j * 64)) * KVC + kvh * HD;
        const float* vb = Vm + ((size_t)(b * TT + j * 64)) * KVC + kvh * HD;
        #pragma unroll
        for (int i = 0; i < 16; i++) {
            int e  = tid + i * 256;
            int c  = e >> 6;
            int kk = e & 63;
            Ks[kk * 68 + c] = kb[(size_t)c * KVC + kk];
            Vs[c * 64 + kk] = vb[(size_t)c * KVC + kk];
        }
        __syncthreads();

        // S = Q K^T (scaled)
        float s[4][4] = {};
        #pragma unroll
        for (int kk = 0; kk < 64; kk++) {
            float a[4], bbv[4];
            *(float4*)a   = *(const float4*)&Qs[kk * 68 + ty * 4];
            *(float4*)bbv = *(const float4*)&Ks[kk * 68 + tx * 4];
            #pragma unroll
            for (int i = 0; i < 4; i++)
                #pragma unroll
                for (int jj = 0; jj < 4; jj++)
                    s[i][jj] = fmaf(a[i], bbv[jj], s[i][jj]);
        }

        if (j == qt) {  // causal mask only on the diagonal tile
            #pragma unroll
            for (int i = 0; i < 4; i++)
                #pragma unroll
                for (int jj = 0; jj < 4; jj++)
                    if (tx * 4 + jj > ty * 4 + i) s[i][jj] = -3.0e38f;
        }

        __syncthreads();   // all threads done reading Ks -> safe to overwrite as P^T
        float* Pst = Ks;

        // online softmax per row (rows distributed over 16 tx-lanes within half-warps)
        #pragma unroll
        for (int i = 0; i < 4; i++) {
            float mx = fmaxf(fmaxf(s[i][0], s[i][1]), fmaxf(s[i][2], s[i][3]));
            mx = fmaxf(mx, __shfl_xor_sync(0xffffffffu, mx, 1));
            mx = fmaxf(mx, __shfl_xor_sync(0xffffffffu, mx, 2));
            mx = fmaxf(mx, __shfl_xor_sync(0xffffffffu, mx, 4));
            mx = fmaxf(mx, __shfl_xor_sync(0xffffffffu, mx, 8));
            float mnew  = fmaxf(m[i], mx);
            float alpha = expf(m[i] - mnew);
            float rs = 0.f;
            #pragma unroll
            for (int jj = 0; jj < 4; jj++) {
                float p = expf(s[i][jj] - mnew);
                rs += p;
                Pst[(tx * 4 + jj) * 68 + ty * 4 + i] = p;
            }
            rs += __shfl_xor_sync(0xffffffffu, rs, 1);
            rs += __shfl_xor_sync(0xffffffffu, rs, 2);
            rs += __shfl_xor_sync(0xffffffffu, rs, 4);
            rs += __shfl_xor_sync(0xffffffffu, rs, 8);
            l[i] = l[i] * alpha + rs;
            m[i] = mnew;
            #pragma unroll
            for (int jj = 0; jj < 4; jj++) o[i][jj] *= alpha;
        }
        __syncthreads();   // P^T fully written

        // O += P @ V
        #pragma unroll
        for (int c = 0; c < 64; c++) {
            float a[4], v4[4];
            *(float4*)a  = *(const float4*)&Pst[c * 68 + ty * 4];
            *(float4*)v4 = *(const float4*)&Vs[c * 64 + tx * 4];
            #pragma unroll
            for (int i = 0; i < 4; i++)
                #pragma unroll
                for (int jj = 0; jj < 4; jj++)
                    o[i][jj] = fmaf(a[i], v4[jj], o[i][jj]);
        }
    }

    float* ob = Om + ((size_t)(b * TT + qt * 64)) * CC + h * HD;
    #pragma unroll
    for (int i = 0; i < 4; i++) {
        float inv = 1.f / l[i];
        #pragma unroll
        for (int jj = 0; jj < 4; jj++)
            ob[(size_t)(ty * 4 + i) * CC + tx * 4 + jj] = o[i][jj] * inv;
    }
}

// ---------------- launch ----------------
extern "C" void kernel_launch(void* const* d_in, const int* in_sizes, int n_in,
                              void* d_out, int out_size)
{
    (void)in_sizes; (void)n_in; (void)out_size;
    const float* x  = (const float*)d_in[0];
    const float* wq = (const float*)d_in[1];
    const float* bq = (const float*)d_in[2];
    const float* wk = (const float*)d_in[3];
    const float* bk = (const float*)d_in[4];
    const float* wv = (const float*)d_in[5];
    const float* bv = (const float*)d_in[6];
    const float* wo = (const float*)d_in[7];
    const float* bo = (const float*)d_in[8];
    float* out = (float*)d_out;

    float *q, *k, *v, *att;
    cudaGetSymbolAddress((void**)&q,   g_q);
    cudaGetSymbolAddress((void**)&k,   g_k);
    cudaGetSymbolAddress((void**)&v,   g_v);
    cudaGetSymbolAddress((void**)&att, g_att);

    // Q/K/V projections (RoPE fused into Q and K epilogues)
    sgemm_kernel<true ><<<dim3(CC  / 64, MM / 64), 256>>>(x, wq, bq, q, MM, CC,  CC);
    sgemm_kernel<true ><<<dim3(KVC / 64, MM / 64), 256>>>(x, wk, bk, k, MM, KVC, CC);
    sgemm_kernel<false><<<dim3(KVC / 64, MM / 64), 256>>>(x, wv, bv, v, MM, KVC, CC);

    // attention
    cudaFuncSetAttribute(attn_kernel, cudaFuncAttributeMaxDynamicSharedMemorySize, ATT_SMEM);
    attn_kernel<<<dim3(TT / 64, NH, BB), 256, ATT_SMEM>>>(q, k, v, att);

    // output projection
    sgemm_kernel<false><<<dim3(CC / 64, MM / 64), 256>>>(att, wo, bo, out, MM, CC, CC);
}